// round 3
// baseline (speedup 1.0000x reference)
#include <cuda_runtime.h>
#include <math.h>

// ---------------- problem constants ----------------
#define NIMG 4
#define BATCH 8
#define SEQ 576
#define DIM 256
#define NHEAD 8
#define DHEAD 32
#define NLAYER 6
#define MLPDIM 512
#define NB (NIMG*BATCH)      // 32
#define TOK (NB*SEQ)         // 18432
#define KPATCH 768           // 3*16*16
#define GRID24 24

// ---------------- scratch (device globals; no allocation allowed) ----------------
__device__ float g_im2col[(long)NIMG*BATCH*SEQ*KPATCH];  // 56.6 MB
__device__ float g_pe[(long)TOK*DIM];                    // 18.9 MB
__device__ float g_qkv[(long)TOK*3*DIM];                 // 56.6 MB
__device__ float g_o[(long)TOK*DIM];                     // 18.9 MB
__device__ float g_feat[BATCH*NIMG*DIM];

// ---------------- tf32 helpers ----------------
__device__ __forceinline__ unsigned f2tf(float f) {
    unsigned u; asm("cvt.rna.tf32.f32 %0, %1;" : "=r"(u) : "f"(f)); return u;
}
__device__ __forceinline__ void mma_tf32(float* d, const unsigned* a, unsigned b0, unsigned b1) {
    asm volatile(
        "mma.sync.aligned.m16n8k8.row.col.f32.tf32.tf32.f32 "
        "{%0,%1,%2,%3},{%4,%5,%6,%7},{%8,%9},{%0,%1,%2,%3};"
        : "+f"(d[0]), "+f"(d[1]), "+f"(d[2]), "+f"(d[3])
        : "r"(a[0]), "r"(a[1]), "r"(a[2]), "r"(a[3]), "r"(b0), "r"(b1));
}

// ---------------- im2col ----------------
__global__ void im2col_k(const float* __restrict__ x) {
    long idx = (long)blockIdx.x*256 + threadIdx.x;
    const long total = (long)NIMG*BATCH*SEQ*KPATCH;
    if (idx >= total) return;
    int k   = (int)(idx % KPATCH);
    long r  = idx / KPATCH;
    int s   = (int)(r % SEQ);
    int b   = (int)((r / SEQ) % BATCH);
    int ni  = (int)(r / ((long)SEQ*BATCH));
    int c   = k >> 8;
    int py  = (k >> 4) & 15;
    int px  = k & 15;
    int gy  = s / GRID24, gx = s % GRID24;
    g_im2col[idx] = x[(((long)b*12 + ni*3 + c)*384 + gy*16 + py)*384 + gx*16 + px];
}

// ---------------- 3xTF32 tensor GEMM: C[M,N] = A[M,K] @ Bw[N,K]^T (+bias)(+pos_enc) ----------------
// 64x64 tile, BK=16, 256 threads (8 warps: 4 m-frags x 2 n-halves).
__global__ __launch_bounds__(256) void gemm_tf32(
    const float* __restrict__ A, const float* __restrict__ Bw, float* __restrict__ C,
    int M, int N, int K,
    const float* __restrict__ bias, const float* __restrict__ pos,
    long strideA, long strideB, long strideC, int strideBias)
{
    A  += (long)blockIdx.z * strideA;
    Bw += (long)blockIdx.z * strideB;
    C  += (long)blockIdx.z * strideC;
    if (bias) bias += (long)blockIdx.z * strideBias;

    __shared__ unsigned Ah[64][20], Al[64][20], Bh[64][20], Bl[64][20];

    const int tid  = threadIdx.x;
    const int lane = tid & 31;
    const int w    = tid >> 5;
    const int r4   = lane >> 2;
    const int c4   = lane & 3;
    const int wm   = w & 3;       // m-frag 0..3 (16 rows each)
    const int wn   = w >> 2;      // n-half 0..1 (32 cols each)
    const int m0   = blockIdx.y * 64;
    const int n0   = blockIdx.x * 64;
    const int lrow = tid >> 2;
    const int lc4  = (tid & 3) * 4;

    float acc[4][4] = {};

    for (int k0 = 0; k0 < K; k0 += 16) {
        float4 av = *(const float4*)&A[(long)(m0 + lrow)*K + k0 + lc4];
        float4 bv = *(const float4*)&Bw[(long)(n0 + lrow)*K + k0 + lc4];
        #pragma unroll
        for (int i = 0; i < 4; i++) {
            float va = (&av.x)[i];
            unsigned h = f2tf(va);
            Ah[lrow][lc4+i] = h;
            Al[lrow][lc4+i] = f2tf(va - __uint_as_float(h));
            float vb = (&bv.x)[i];
            unsigned hb = f2tf(vb);
            Bh[lrow][lc4+i] = hb;
            Bl[lrow][lc4+i] = f2tf(vb - __uint_as_float(hb));
        }
        __syncthreads();
        #pragma unroll
        for (int kk = 0; kk < 2; kk++) {
            int kb = kk*8;
            unsigned ah[4], al[4];
            ah[0] = Ah[wm*16 + r4    ][kb + c4];
            ah[1] = Ah[wm*16 + r4 + 8][kb + c4];
            ah[2] = Ah[wm*16 + r4    ][kb + c4 + 4];
            ah[3] = Ah[wm*16 + r4 + 8][kb + c4 + 4];
            al[0] = Al[wm*16 + r4    ][kb + c4];
            al[1] = Al[wm*16 + r4 + 8][kb + c4];
            al[2] = Al[wm*16 + r4    ][kb + c4 + 4];
            al[3] = Al[wm*16 + r4 + 8][kb + c4 + 4];
            #pragma unroll
            for (int nt = 0; nt < 4; nt++) {
                unsigned bh0 = Bh[wn*32 + nt*8 + r4][kb + c4];
                unsigned bh1 = Bh[wn*32 + nt*8 + r4][kb + c4 + 4];
                unsigned bl0 = Bl[wn*32 + nt*8 + r4][kb + c4];
                unsigned bl1 = Bl[wn*32 + nt*8 + r4][kb + c4 + 4];
                mma_tf32(acc[nt], ah, bh0, bh1);
                mma_tf32(acc[nt], al, bh0, bh1);
                mma_tf32(acc[nt], ah, bl0, bl1);
            }
        }
        __syncthreads();
    }

    #pragma unroll
    for (int nt = 0; nt < 4; nt++) {
        int n = n0 + wn*32 + nt*8 + c4*2;
        float2 bb = {0.f, 0.f};
        if (bias) { bb.x = bias[n]; bb.y = bias[n+1]; }
        int row0 = m0 + wm*16 + r4;
        int row1 = row0 + 8;
        float2 v0 = make_float2(acc[nt][0] + bb.x, acc[nt][1] + bb.y);
        float2 v1 = make_float2(acc[nt][2] + bb.x, acc[nt][3] + bb.y);
        if (pos) {
            const float* p0 = pos + (long)(row0 % SEQ)*DIM + n;
            const float* p1 = pos + (long)(row1 % SEQ)*DIM + n;
            v0.x += p0[0]; v0.y += p0[1];
            v1.x += p1[0]; v1.y += p1[1];
        }
        *(float2*)&C[(long)row0*N + n] = v0;
        *(float2*)&C[(long)row1*N + n] = v1;
    }
}

// ---------------- fused attention (tf32 tensor-core, Q-split, E-as-tf32) ----------------
#define KSTR 36
#define SSTR 580
#define ATTN_FLOATS (SEQ*KSTR + 32*SSTR + 512 + 32 + 32 + 32)
#define ATTN_SMEM (ATTN_FLOATS*4)

__global__ __launch_bounds__(256, 1) void attn_mma(
    const float* __restrict__ qkv, float* __restrict__ o,
    float* __restrict__ attn_out, int layer)
{
    extern __shared__ float sm[];
    unsigned* Ks   = (unsigned*)sm;             // [576][36] tf32 K; Vs overlay [32][580]
    float* Ss      = sm + SEQ*KSTR;             // [32][580] E (tf32-valued floats)
    float* pbufA   = Ss + 32*SSTR;              // [32][8] exact sums / row maxes
    float* pbufB   = pbufA + 256;               // [32][8] rounded sums
    float* rowmax  = pbufB + 256;               // [32]
    float* rinv0   = rowmax + 32;               // [32] 1/sum(exact e)   (attn path)
    float* rinv1   = rinv0 + 32;                // [32] 1/sum(rounded e) (PV path)

    const int tid  = threadIdx.x;
    const int lane = tid & 31;
    const int w    = tid >> 5;
    const int r4   = lane >> 2;
    const int c4   = lane & 3;
    const int qt   = blockIdx.x;                // 0..17
    const int nb   = blockIdx.y;                // 0..31
    const float* qbase = qkv + (long)nb*SEQ*768;
    const float SC = 0.17677669529663687f;      // 1/sqrt(32)

    float am[2][9][4];
    #pragma unroll
    for (int mt = 0; mt < 2; mt++)
        #pragma unroll
        for (int nt = 0; nt < 9; nt++)
            #pragma unroll
            for (int i = 0; i < 4; i++) am[mt][nt][i] = 0.f;

    for (int h = 0; h < NHEAD; h++) {
        __syncthreads();                        // S0
        // ---- P1: load K tile [576][32] as tf32 ----
        for (int t = tid; t < SEQ*8; t += 256) {
            int kr = t >> 3, cc = (t & 7)*4;
            float4 v = *(const float4*)&qbase[(long)kr*768 + 256 + h*32 + cc];
            unsigned* d = &Ks[kr*KSTR + cc];
            d[0] = f2tf(v.x); d[1] = f2tf(v.y); d[2] = f2tf(v.z); d[3] = f2tf(v.w);
        }
        __syncthreads();                        // S1

        // ---- P2: S = Q K^T, Q split hi+lo (2xTF32) ----
        float acc[2][9][4];
        #pragma unroll
        for (int mt = 0; mt < 2; mt++)
            #pragma unroll
            for (int nt = 0; nt < 9; nt++)
                #pragma unroll
                for (int i = 0; i < 4; i++) acc[mt][nt][i] = 0.f;

        #pragma unroll
        for (int kc = 0; kc < 4; kc++) {
            unsigned a0h[4], a0l[4], a1h[4], a1l[4];
            {
                const float* qp = qbase + (long)(qt*32 + r4)*768 + h*32 + kc*8 + c4;
                float q0 = qp[0]*SC, q1 = qp[8*768]*SC, q2 = qp[4]*SC, q3 = qp[8*768+4]*SC;
                a0h[0]=f2tf(q0); a0l[0]=f2tf(q0-__uint_as_float(a0h[0]));
                a0h[1]=f2tf(q1); a0l[1]=f2tf(q1-__uint_as_float(a0h[1]));
                a0h[2]=f2tf(q2); a0l[2]=f2tf(q2-__uint_as_float(a0h[2]));
                a0h[3]=f2tf(q3); a0l[3]=f2tf(q3-__uint_as_float(a0h[3]));
                const float* qp1 = qp + 16*768;
                float p0 = qp1[0]*SC, p1 = qp1[8*768]*SC, p2 = qp1[4]*SC, p3 = qp1[8*768+4]*SC;
                a1h[0]=f2tf(p0); a1l[0]=f2tf(p0-__uint_as_float(a1h[0]));
                a1h[1]=f2tf(p1); a1l[1]=f2tf(p1-__uint_as_float(a1h[1]));
                a1h[2]=f2tf(p2); a1l[2]=f2tf(p2-__uint_as_float(a1h[2]));
                a1h[3]=f2tf(p3); a1l[3]=f2tf(p3-__uint_as_float(a1h[3]));
            }
            const unsigned* kb = &Ks[(w*72 + r4)*KSTR + kc*8 + c4];
            #pragma unroll
            for (int nt = 0; nt < 9; nt++) {
                unsigned b0 = kb[nt*8*KSTR], b1 = kb[nt*8*KSTR + 4];
                mma_tf32(acc[0][nt], a0h, b0, b1);
                mma_tf32(acc[0][nt], a0l, b0, b1);
                mma_tf32(acc[1][nt], a1h, b0, b1);
                mma_tf32(acc[1][nt], a1l, b0, b1);
            }
        }
        // partial row max
        {
            float pm[4] = {-1e30f, -1e30f, -1e30f, -1e30f};
            #pragma unroll
            for (int mt = 0; mt < 2; mt++)
                #pragma unroll
                for (int nt = 0; nt < 9; nt++) {
                    pm[mt*2+0] = fmaxf(pm[mt*2+0], fmaxf(acc[mt][nt][0], acc[mt][nt][1]));
                    pm[mt*2+1] = fmaxf(pm[mt*2+1], fmaxf(acc[mt][nt][2], acc[mt][nt][3]));
                }
            #pragma unroll
            for (int s = 0; s < 4; s++) {
                pm[s] = fmaxf(pm[s], __shfl_xor_sync(0xffffffffu, pm[s], 1));
                pm[s] = fmaxf(pm[s], __shfl_xor_sync(0xffffffffu, pm[s], 2));
            }
            if (c4 == 0) {
                #pragma unroll
                for (int s = 0; s < 4; s++) pbufA[(s*8 + r4)*8 + w] = pm[s];
            }
        }
        __syncthreads();                        // S2
        // ---- P3: rowmax reduce + load V^T (overwrites K region) ----
        if (tid < 32) {
            float m = pbufA[tid*8];
            #pragma unroll
            for (int i = 1; i < 8; i++) m = fmaxf(m, pbufA[tid*8 + i]);
            rowmax[tid] = m;
        }
        {
            unsigned* Vs = Ks;                  // [32][580] tf32 V^T
            int dh = lane, kb0 = w;
            #pragma unroll 2
            for (int it = 0; it < 18; it++) {
                int key4 = (kb0 + it*8)*4;
                const float* vp = qbase + (long)key4*768 + 512 + h*32 + dh;
                uint4 pk;
                pk.x = f2tf(vp[0]);
                pk.y = f2tf(vp[768]);
                pk.z = f2tf(vp[2*768]);
                pk.w = f2tf(vp[3*768]);
                *(uint4*)&Vs[dh*SSTR + key4] = pk;
            }
        }
        __syncthreads();                        // S3
        // ---- P4: e = exp(s - rowmax); Ss <- tf32(e); dual sums ----
        {
            float rm[4] = {rowmax[r4], rowmax[r4+8], rowmax[r4+16], rowmax[r4+24]};
            float psA[4] = {0.f,0.f,0.f,0.f};
            float psB[4] = {0.f,0.f,0.f,0.f};
            #pragma unroll
            for (int mt = 0; mt < 2; mt++) {
                float* row0 = &Ss[(mt*16 + r4)*SSTR + w*72 + c4*2];
                float* row1 = row0 + 8*SSTR;
                #pragma unroll
                for (int nt = 0; nt < 9; nt++) {
                    float e0 = __expf(acc[mt][nt][0] - rm[mt*2]);
                    float e1 = __expf(acc[mt][nt][1] - rm[mt*2]);
                    float e2 = __expf(acc[mt][nt][2] - rm[mt*2+1]);
                    float e3 = __expf(acc[mt][nt][3] - rm[mt*2+1]);
                    acc[mt][nt][0] = e0; acc[mt][nt][1] = e1;
                    acc[mt][nt][2] = e2; acc[mt][nt][3] = e3;
                    psA[mt*2]   += e0 + e1;
                    psA[mt*2+1] += e2 + e3;
                    float f0 = __uint_as_float(f2tf(e0));
                    float f1 = __uint_as_float(f2tf(e1));
                    float f2v = __uint_as_float(f2tf(e2));
                    float f3 = __uint_as_float(f2tf(e3));
                    psB[mt*2]   += f0 + f1;
                    psB[mt*2+1] += f2v + f3;
                    *(float2*)&row0[nt*8] = make_float2(f0, f1);
                    *(float2*)&row1[nt*8] = make_float2(f2v, f3);
                }
            }
            #pragma unroll
            for (int s = 0; s < 4; s++) {
                psA[s] += __shfl_xor_sync(0xffffffffu, psA[s], 1);
                psA[s] += __shfl_xor_sync(0xffffffffu, psA[s], 2);
                psB[s] += __shfl_xor_sync(0xffffffffu, psB[s], 1);
                psB[s] += __shfl_xor_sync(0xffffffffu, psB[s], 2);
            }
            if (c4 == 0) {
                #pragma unroll
                for (int s = 0; s < 4; s++) {
                    pbufA[(s*8 + r4)*8 + w] = psA[s];
                    pbufB[(s*8 + r4)*8 + w] = psB[s];
                }
            }
        }
        __syncthreads();                        // S4
        if (tid < 32) {
            float sa = 0.f, sb = 0.f;
            #pragma unroll
            for (int i = 0; i < 8; i++) { sa += pbufA[tid*8 + i]; sb += pbufB[tid*8 + i]; }
            rinv0[tid] = __frcp_rn(sa);
            rinv1[tid] = __frcp_rn(sb);
        }
        __syncthreads();                        // S5
        // ---- P5: Am += exact e * rinv0 / 8 (register-resident, layout matches P2) ----
        {
            float ra[4] = {rinv0[r4]*0.125f, rinv0[r4+8]*0.125f,
                           rinv0[r4+16]*0.125f, rinv0[r4+24]*0.125f};
            #pragma unroll
            for (int mt = 0; mt < 2; mt++)
                #pragma unroll
                for (int nt = 0; nt < 9; nt++) {
                    am[mt][nt][0] += acc[mt][nt][0] * ra[mt*2];
                    am[mt][nt][1] += acc[mt][nt][1] * ra[mt*2];
                    am[mt][nt][2] += acc[mt][nt][2] * ra[mt*2+1];
                    am[mt][nt][3] += acc[mt][nt][3] * ra[mt*2+1];
                }
        }
        // ---- P6: O = (E V) * rinv1 (E read as tf32 directly, zero cvt) ----
        {
            const int mt6 = w >> 2, nt6 = w & 3;
            float dv[4] = {0.f, 0.f, 0.f, 0.f};
            const unsigned* Es = (const unsigned*)Ss;
            const unsigned* Vs = Ks;
            const unsigned* e0b = &Es[(mt6*16 + r4)*SSTR + c4];
            const unsigned* e1b = e0b + 8*SSTR;
            const unsigned* vb  = &Vs[(nt6*8 + r4)*SSTR + c4];
            #pragma unroll 8
            for (int kc = 0; kc < 72; kc++) {
                unsigned a[4];
                a[0] = e0b[kc*8]; a[1] = e1b[kc*8];
                a[2] = e0b[kc*8 + 4]; a[3] = e1b[kc*8 + 4];
                mma_tf32(dv, a, vb[kc*8], vb[kc*8 + 4]);
            }
            float ri0 = rinv1[mt6*16 + r4], ri1 = rinv1[mt6*16 + r4 + 8];
            long orow = (long)(nb*SEQ + qt*32 + mt6*16 + r4)*DIM + h*32 + nt6*8 + c4*2;
            *(float2*)&o[orow]          = make_float2(dv[0]*ri0, dv[1]*ri0);
            *(float2*)&o[orow + 8*DIM]  = make_float2(dv[2]*ri1, dv[3]*ri1);
        }
    }
    // ---- final: write head-mean attention from registers ----
    float* aout = attn_out + (long)(layer*NB + nb)*SEQ*SEQ + (long)qt*32*SEQ;
    #pragma unroll
    for (int mt = 0; mt < 2; mt++)
        #pragma unroll
        for (int half = 0; half < 2; half++) {
            int row = mt*16 + r4 + half*8;
            #pragma unroll
            for (int nt = 0; nt < 9; nt++) {
                int col = w*72 + nt*8 + c4*2;
                *(float2*)&aout[(long)row*SEQ + col] =
                    make_float2(am[mt][nt][half*2], am[mt][nt][half*2+1]);
            }
        }
}

// ---------------- feature mean over sequence ----------------
__global__ void feat_k(void) {
    int ni = blockIdx.x, b = blockIdx.y, d = threadIdx.x;
    const float* p = g_pe + ((long)(ni*BATCH + b)*SEQ)*DIM + d;
    float s = 0.f;
    for (int t = 0; t < SEQ; t++) s += p[(long)t*DIM];
    g_feat[b*(NIMG*DIM) + ni*DIM + d] = s * (1.0f/576.0f);
}

// ---------------- MLP head ----------------
__global__ void head_k(const float* __restrict__ w1, const float* __restrict__ b1,
                       const float* __restrict__ w2, const float* __restrict__ b2,
                       float* __restrict__ out) {
    __shared__ float fs[NIMG*DIM];
    __shared__ float hs[MLPDIM];
    int b = blockIdx.x, tid = threadIdx.x;
    for (int t = tid; t < NIMG*DIM; t += MLPDIM) fs[t] = g_feat[b*NIMG*DIM + t];
    __syncthreads();
    float a = b1[tid];
    const float* wr = w1 + (long)tid*(NIMG*DIM);
    for (int d2 = 0; d2 < NIMG*DIM; d2++) a += fs[d2]*wr[d2];
    hs[tid] = fmaxf(a, 0.f) * w2[tid];
    __syncthreads();
    for (int st = 256; st > 0; st >>= 1) {
        if (tid < st) hs[tid] += hs[tid + st];
        __syncthreads();
    }
    if (tid == 0) out[b] = hs[0] + b2[0];
}

// ---------------- launch ----------------
extern "C" void kernel_launch(void* const* d_in, const int* in_sizes, int n_in,
                              void* d_out, int out_size) {
    const float* x      = (const float*)d_in[0];
    const float* conv_w = (const float*)d_in[1];
    const float* conv_b = (const float*)d_in[2];
    const float* pos_e  = (const float*)d_in[3];
    const float* in_w   = (const float*)d_in[4];
    const float* in_b   = (const float*)d_in[5];
    const float* out_w  = (const float*)d_in[6];
    const float* out_b  = (const float*)d_in[7];
    const float* hw1    = (const float*)d_in[8];
    const float* hb1    = (const float*)d_in[9];
    const float* hw2    = (const float*)d_in[10];
    const float* hb2    = (const float*)d_in[11];

    float* out  = (float*)d_out;            // [8]
    float* attn = out + BATCH;              // [6,4,8,576,576]

    cudaFuncSetAttribute(attn_mma, cudaFuncAttributeMaxDynamicSharedMemorySize, ATTN_SMEM);

    float *im2col_p, *pe_p, *qkv_p, *o_p;
    cudaGetSymbolAddress((void**)&im2col_p, g_im2col);
    cudaGetSymbolAddress((void**)&pe_p,     g_pe);
    cudaGetSymbolAddress((void**)&qkv_p,    g_qkv);
    cudaGetSymbolAddress((void**)&o_p,      g_o);

    // 1) im2col
    {
        long total = (long)NIMG*BATCH*SEQ*KPATCH;
        im2col_k<<<(int)((total + 255)/256), 256>>>(x);
    }
    // 2) patch-embed GEMM per image, + conv_b + pos_enc
    {
        dim3 g(DIM/64, (BATCH*SEQ)/64, NIMG);
        gemm_tf32<<<g, 256>>>(im2col_p, conv_w, pe_p,
                              BATCH*SEQ, DIM, KPATCH,
                              conv_b, pos_e,
                              (long)BATCH*SEQ*KPATCH, (long)DIM*KPATCH,
                              (long)BATCH*SEQ*DIM, DIM);
    }
    // 3) transformer layers
    for (int l = 0; l < NLAYER; l++) {
        {
            dim3 g((3*DIM)/64, TOK/64, 1);
            gemm_tf32<<<g, 256>>>(pe_p, in_w + (long)l*3*DIM*DIM, qkv_p,
                                  TOK, 3*DIM, DIM,
                                  in_b + (long)l*3*DIM, nullptr, 0, 0, 0, 0);
        }
        {
            dim3 g(SEQ/32, NB, 1);
            attn_mma<<<g, 256, ATTN_SMEM>>>(qkv_p, o_p, attn, l);
        }
        {
            dim3 g(DIM/64, TOK/64, 1);
            gemm_tf32<<<g, 256>>>(o_p, out_w + (long)l*DIM*DIM, pe_p,
                                  TOK, DIM, DIM,
                                  out_b + (long)l*DIM, nullptr, 0, 0, 0, 0);
        }
    }
    // 4) sequence-mean features + MLP head
    {
        dim3 g(NIMG, BATCH);
        feat_k<<<g, DIM>>>();
    }
    head_k<<<BATCH, MLPDIM>>>(hw1, hb1, hw2, hb2, out);
}

// round 4
// speedup vs baseline: 1.0599x; 1.0599x over previous
#include <cuda_runtime.h>
#include <math.h>

// ---------------- problem constants ----------------
#define NIMG 4
#define BATCH 8
#define SEQ 576
#define DIM 256
#define NHEAD 8
#define DHEAD 32
#define NLAYER 6
#define MLPDIM 512
#define NB (NIMG*BATCH)      // 32
#define TOK (NB*SEQ)         // 18432
#define KPATCH 768           // 3*16*16
#define GRID24 24

// ---------------- scratch (device globals; no allocation allowed) ----------------
__device__ float g_im2col[(long)NIMG*BATCH*SEQ*KPATCH];  // 56.6 MB
__device__ float g_pe[(long)TOK*DIM];                    // 18.9 MB
__device__ float g_qkv[(long)TOK*3*DIM];                 // 56.6 MB
__device__ float g_o[(long)TOK*DIM];                     // 18.9 MB
__device__ float g_feat[BATCH*NIMG*DIM];

// ---------------- tf32 helpers ----------------
__device__ __forceinline__ unsigned f2tf(float f) {
    unsigned u; asm("cvt.rna.tf32.f32 %0, %1;" : "=r"(u) : "f"(f)); return u;
}
__device__ __forceinline__ void mma_tf32(float* d, const unsigned* a, unsigned b0, unsigned b1) {
    asm volatile(
        "mma.sync.aligned.m16n8k8.row.col.f32.tf32.tf32.f32 "
        "{%0,%1,%2,%3},{%4,%5,%6,%7},{%8,%9},{%0,%1,%2,%3};"
        : "+f"(d[0]), "+f"(d[1]), "+f"(d[2]), "+f"(d[3])
        : "r"(a[0]), "r"(a[1]), "r"(a[2]), "r"(a[3]), "r"(b0), "r"(b1));
}

// ---------------- im2col ----------------
__global__ void im2col_k(const float* __restrict__ x) {
    long idx = (long)blockIdx.x*256 + threadIdx.x;
    const long total = (long)NIMG*BATCH*SEQ*KPATCH;
    if (idx >= total) return;
    int k   = (int)(idx % KPATCH);
    long r  = idx / KPATCH;
    int s   = (int)(r % SEQ);
    int b   = (int)((r / SEQ) % BATCH);
    int ni  = (int)(r / ((long)SEQ*BATCH));
    int c   = k >> 8;
    int py  = (k >> 4) & 15;
    int px  = k & 15;
    int gy  = s / GRID24, gx = s % GRID24;
    g_im2col[idx] = x[(((long)b*12 + ni*3 + c)*384 + gy*16 + py)*384 + gx*16 + px];
}

// ---------------- scalar SGEMM (exact fp32): C[M,N] = A[M,K] @ Bw[N,K]^T ----------------
__global__ __launch_bounds__(256) void sgemm64(
    const float* __restrict__ A, const float* __restrict__ Bw, float* __restrict__ C,
    int M, int N, int K,
    const float* __restrict__ bias, const float* __restrict__ pos,
    long strideA, long strideB, long strideC, int strideBias)
{
    A  += (long)blockIdx.z * strideA;
    Bw += (long)blockIdx.z * strideB;
    C  += (long)blockIdx.z * strideC;
    if (bias) bias += (long)blockIdx.z * strideBias;

    __shared__ float As[16][68];
    __shared__ float Bs[16][68];

    int tid  = threadIdx.x;
    int m0   = blockIdx.y * 64;
    int n0   = blockIdx.x * 64;
    int arow = tid >> 2;
    int ac4  = (tid & 3) * 4;
    int tm   = tid >> 4;
    int tn   = tid & 15;

    float acc[4][4] = {};

    for (int k0 = 0; k0 < K; k0 += 16) {
        float4 av = *(const float4*)&A[(long)(m0 + arow)*K + k0 + ac4];
        float4 bv = *(const float4*)&Bw[(long)(n0 + arow)*K + k0 + ac4];
        As[ac4+0][arow] = av.x; As[ac4+1][arow] = av.y;
        As[ac4+2][arow] = av.z; As[ac4+3][arow] = av.w;
        Bs[ac4+0][arow] = bv.x; Bs[ac4+1][arow] = bv.y;
        Bs[ac4+2][arow] = bv.z; Bs[ac4+3][arow] = bv.w;
        __syncthreads();
        #pragma unroll
        for (int kk = 0; kk < 16; kk++) {
            float4 a = *(const float4*)&As[kk][tm*4];
            float4 b = *(const float4*)&Bs[kk][tn*4];
            acc[0][0] += a.x*b.x; acc[0][1] += a.x*b.y; acc[0][2] += a.x*b.z; acc[0][3] += a.x*b.w;
            acc[1][0] += a.y*b.x; acc[1][1] += a.y*b.y; acc[1][2] += a.y*b.z; acc[1][3] += a.y*b.w;
            acc[2][0] += a.z*b.x; acc[2][1] += a.z*b.y; acc[2][2] += a.z*b.z; acc[2][3] += a.z*b.w;
            acc[3][0] += a.w*b.x; acc[3][1] += a.w*b.y; acc[3][2] += a.w*b.z; acc[3][3] += a.w*b.w;
        }
        __syncthreads();
    }

    int n = n0 + tn*4;
    float4 bb = {0.f,0.f,0.f,0.f};
    if (bias) { bb.x = bias[n]; bb.y = bias[n+1]; bb.z = bias[n+2]; bb.w = bias[n+3]; }
    #pragma unroll
    for (int ii = 0; ii < 4; ii++) {
        int m = m0 + tm*4 + ii;
        float4 v;
        v.x = acc[ii][0] + bb.x; v.y = acc[ii][1] + bb.y;
        v.z = acc[ii][2] + bb.z; v.w = acc[ii][3] + bb.w;
        if (pos) {
            const float* pr = pos + (long)(m % SEQ)*DIM + n;
            v.x += pr[0]; v.y += pr[1]; v.z += pr[2]; v.w += pr[3];
        }
        *(float4*)&C[(long)m*N + n] = v;
    }
}

// ---------------- fused attention (tf32 mma, 16-query CTAs, 2 CTA/SM) ----------------
#define KT_STR 580
#define SSTR 580
#define ATTN_FLOATS (32*KT_STR + 16*SSTR + 128 + 128 + 16 + 16 + 16)
#define ATTN_SMEM (ATTN_FLOATS*4)   // 112,576 B

__global__ __launch_bounds__(256, 2) void attn_mma(
    const float* __restrict__ qkv, float* __restrict__ o,
    float* __restrict__ attn_out, int layer)
{
    extern __shared__ float sm[];
    unsigned* Kt   = (unsigned*)sm;             // [32 dh][580 key] tf32 K^T; V^T overlay
    float* Ss      = sm + 32*KT_STR;            // [16 q][580 key] E (tf32-valued)
    float* pbufA   = Ss + 16*SSTR;              // [16][8]
    float* pbufB   = pbufA + 128;               // [16][8]
    float* rowmax  = pbufB + 128;               // [16]
    float* rinv0   = rowmax + 16;               // [16] 1/sum(exact e)   (attn path)
    float* rinv1   = rinv0 + 16;                // [16] 1/sum(rounded e) (PV path)

    const int tid  = threadIdx.x;
    const int lane = tid & 31;
    const int w    = tid >> 5;
    const int r4   = lane >> 2;
    const int c4   = lane & 3;
    const int qt   = blockIdx.x;                // 0..35
    const int nb   = blockIdx.y;                // 0..31
    const float* qbase = qkv + (long)nb*SEQ*768;
    const float SC = 0.17677669529663687f;      // 1/sqrt(32)

    float am[9][4];
    #pragma unroll
    for (int nt = 0; nt < 9; nt++)
        #pragma unroll
        for (int i = 0; i < 4; i++) am[nt][i] = 0.f;

    for (int h = 0; h < NHEAD; h++) {
        __syncthreads();                        // S0: Kt/Ss free from prev head
        // ---- P1: load K^T [32 dh][576 keys] as tf32 (transposed store) ----
        {
            #pragma unroll 2
            for (int it = 0; it < 18; it++) {
                int key4 = (w + it*8)*4;
                const float* kp = qbase + (long)key4*768 + 256 + h*32 + lane;
                uint4 pk;
                pk.x = f2tf(kp[0]);
                pk.y = f2tf(kp[768]);
                pk.z = f2tf(kp[2*768]);
                pk.w = f2tf(kp[3*768]);
                *(uint4*)&Kt[lane*KT_STR + key4] = pk;
            }
        }
        __syncthreads();                        // S1

        // ---- P2: S = Q K^T, Q split hi+lo (2xTF32); warp w -> keys [w*72,+72) ----
        float acc[9][4];
        #pragma unroll
        for (int nt = 0; nt < 9; nt++)
            #pragma unroll
            for (int i = 0; i < 4; i++) acc[nt][i] = 0.f;

        #pragma unroll
        for (int kc = 0; kc < 4; kc++) {
            unsigned ah[4], al[4];
            {
                const float* qp = qbase + (long)(qt*16 + r4)*768 + h*32 + kc*8 + c4;
                float q0 = qp[0]*SC, q1 = qp[8*768]*SC, q2 = qp[4]*SC, q3 = qp[8*768+4]*SC;
                ah[0]=f2tf(q0); al[0]=f2tf(q0-__uint_as_float(ah[0]));
                ah[1]=f2tf(q1); al[1]=f2tf(q1-__uint_as_float(ah[1]));
                ah[2]=f2tf(q2); al[2]=f2tf(q2-__uint_as_float(ah[2]));
                ah[3]=f2tf(q3); al[3]=f2tf(q3-__uint_as_float(ah[3]));
            }
            const unsigned* kb  = &Kt[(kc*8 + c4)*KT_STR + w*72 + r4];
            const unsigned* kb4 = kb + 4*KT_STR;
            #pragma unroll
            for (int nt = 0; nt < 9; nt++) {
                unsigned b0 = kb[nt*8], b1 = kb4[nt*8];
                mma_tf32(acc[nt], ah, b0, b1);
                mma_tf32(acc[nt], al, b0, b1);
            }
        }
        // partial row max
        {
            float pm[2] = {-1e30f, -1e30f};
            #pragma unroll
            for (int nt = 0; nt < 9; nt++) {
                pm[0] = fmaxf(pm[0], fmaxf(acc[nt][0], acc[nt][1]));
                pm[1] = fmaxf(pm[1], fmaxf(acc[nt][2], acc[nt][3]));
            }
            #pragma unroll
            for (int s = 0; s < 2; s++) {
                pm[s] = fmaxf(pm[s], __shfl_xor_sync(0xffffffffu, pm[s], 1));
                pm[s] = fmaxf(pm[s], __shfl_xor_sync(0xffffffffu, pm[s], 2));
            }
            if (c4 == 0) {
                pbufA[r4*8 + w]     = pm[0];
                pbufA[(r4+8)*8 + w] = pm[1];
            }
        }
        __syncthreads();                        // S2
        // ---- P3: rowmax reduce + load V^T (overwrites Kt) ----
        if (tid < 16) {
            float m = pbufA[tid*8];
            #pragma unroll
            for (int i = 1; i < 8; i++) m = fmaxf(m, pbufA[tid*8 + i]);
            rowmax[tid] = m;
        }
        {
            #pragma unroll 2
            for (int it = 0; it < 18; it++) {
                int key4 = (w + it*8)*4;
                const float* vp = qbase + (long)key4*768 + 512 + h*32 + lane;
                uint4 pk;
                pk.x = f2tf(vp[0]);
                pk.y = f2tf(vp[768]);
                pk.z = f2tf(vp[2*768]);
                pk.w = f2tf(vp[3*768]);
                *(uint4*)&Kt[lane*KT_STR + key4] = pk;
            }
        }
        __syncthreads();                        // S3
        // ---- P4: e = exp(s - rowmax); Ss <- tf32(e); dual sums ----
        {
            float rm0 = rowmax[r4], rm1 = rowmax[r4+8];
            float psA[2] = {0.f,0.f};
            float psB[2] = {0.f,0.f};
            float* row0 = &Ss[r4*SSTR + w*72 + c4*2];
            float* row1 = row0 + 8*SSTR;
            #pragma unroll
            for (int nt = 0; nt < 9; nt++) {
                float e0 = __expf(acc[nt][0] - rm0);
                float e1 = __expf(acc[nt][1] - rm0);
                float e2 = __expf(acc[nt][2] - rm1);
                float e3 = __expf(acc[nt][3] - rm1);
                acc[nt][0] = e0; acc[nt][1] = e1;
                acc[nt][2] = e2; acc[nt][3] = e3;
                psA[0] += e0 + e1;
                psA[1] += e2 + e3;
                float f0 = __uint_as_float(f2tf(e0));
                float f1 = __uint_as_float(f2tf(e1));
                float f2v = __uint_as_float(f2tf(e2));
                float f3 = __uint_as_float(f2tf(e3));
                psB[0] += f0 + f1;
                psB[1] += f2v + f3;
                *(float2*)&row0[nt*8] = make_float2(f0, f1);
                *(float2*)&row1[nt*8] = make_float2(f2v, f3);
            }
            #pragma unroll
            for (int s = 0; s < 2; s++) {
                psA[s] += __shfl_xor_sync(0xffffffffu, psA[s], 1);
                psA[s] += __shfl_xor_sync(0xffffffffu, psA[s], 2);
                psB[s] += __shfl_xor_sync(0xffffffffu, psB[s], 1);
                psB[s] += __shfl_xor_sync(0xffffffffu, psB[s], 2);
            }
            if (c4 == 0) {
                pbufA[r4*8 + w]     = psA[0];
                pbufA[(r4+8)*8 + w] = psA[1];
                pbufB[r4*8 + w]     = psB[0];
                pbufB[(r4+8)*8 + w] = psB[1];
            }
        }
        __syncthreads();                        // S4
        if (tid < 16) {
            float sa = 0.f, sb = 0.f;
            #pragma unroll
            for (int i = 0; i < 8; i++) { sa += pbufA[tid*8 + i]; sb += pbufB[tid*8 + i]; }
            rinv0[tid] = __frcp_rn(sa);
            rinv1[tid] = __frcp_rn(sb);
        }
        __syncthreads();                        // S5
        // ---- P5: Am += exact e * rinv0 / 8 (registers) ----
        {
            float ra0 = rinv0[r4]*0.125f, ra1 = rinv0[r4+8]*0.125f;
            #pragma unroll
            for (int nt = 0; nt < 9; nt++) {
                am[nt][0] += acc[nt][0] * ra0;
                am[nt][1] += acc[nt][1] * ra0;
                am[nt][2] += acc[nt][2] * ra1;
                am[nt][3] += acc[nt][3] * ra1;
            }
        }
        // ---- P6: O = (E V) * rinv1; keys split across warp pairs ----
        {
            const int nt6 = w & 3, half = w >> 2;
            float dv[4] = {0.f, 0.f, 0.f, 0.f};
            const unsigned* Es  = (const unsigned*)Ss;
            const unsigned* e0b = &Es[r4*SSTR + half*288 + c4];
            const unsigned* e1b = e0b + 8*SSTR;
            const unsigned* vb  = &Kt[(nt6*8 + r4)*KT_STR + half*288 + c4];
            #pragma unroll 6
            for (int kc = 0; kc < 36; kc++) {
                unsigned a[4];
                a[0] = e0b[kc*8]; a[1] = e1b[kc*8];
                a[2] = e0b[kc*8 + 4]; a[3] = e1b[kc*8 + 4];
                mma_tf32(dv, a, vb[kc*8], vb[kc*8 + 4]);
            }
            __syncthreads();                    // S6a: all E/V smem reads done
            if (half == 1)
                *(float4*)&Ss[(nt6*32 + lane)*4] = make_float4(dv[0], dv[1], dv[2], dv[3]);
            __syncthreads();                    // S6b
            if (half == 0) {
                float4 p = *(float4*)&Ss[(nt6*32 + lane)*4];
                dv[0] += p.x; dv[1] += p.y; dv[2] += p.z; dv[3] += p.w;
                float ri0 = rinv1[r4], ri1 = rinv1[r4+8];
                long orow = (long)(nb*SEQ + qt*16 + r4)*DIM + h*32 + nt6*8 + c4*2;
                *(float2*)&o[orow]         = make_float2(dv[0]*ri0, dv[1]*ri0);
                *(float2*)&o[orow + 8*DIM] = make_float2(dv[2]*ri1, dv[3]*ri1);
            }
        }
    }
    // ---- final: write head-mean attention from registers ----
    float* aout = attn_out + (long)(layer*NB + nb)*SEQ*SEQ + (long)qt*16*SEQ;
    #pragma unroll
    for (int nt = 0; nt < 9; nt++) {
        int col = w*72 + nt*8 + c4*2;
        *(float2*)&aout[(long)r4*SEQ + col]     = make_float2(am[nt][0], am[nt][1]);
        *(float2*)&aout[(long)(r4+8)*SEQ + col] = make_float2(am[nt][2], am[nt][3]);
    }
}

// ---------------- feature mean over sequence ----------------
__global__ void feat_k(void) {
    int ni = blockIdx.x, b = blockIdx.y, d = threadIdx.x;
    const float* p = g_pe + ((long)(ni*BATCH + b)*SEQ)*DIM + d;
    float s = 0.f;
    for (int t = 0; t < SEQ; t++) s += p[(long)t*DIM];
    g_feat[b*(NIMG*DIM) + ni*DIM + d] = s * (1.0f/576.0f);
}

// ---------------- MLP head ----------------
__global__ void head_k(const float* __restrict__ w1, const float* __restrict__ b1,
                       const float* __restrict__ w2, const float* __restrict__ b2,
                       float* __restrict__ out) {
    __shared__ float fs[NIMG*DIM];
    __shared__ float hs[MLPDIM];
    int b = blockIdx.x, tid = threadIdx.x;
    for (int t = tid; t < NIMG*DIM; t += MLPDIM) fs[t] = g_feat[b*NIMG*DIM + t];
    __syncthreads();
    float a = b1[tid];
    const float* wr = w1 + (long)tid*(NIMG*DIM);
    for (int d2 = 0; d2 < NIMG*DIM; d2++) a += fs[d2]*wr[d2];
    hs[tid] = fmaxf(a, 0.f) * w2[tid];
    __syncthreads();
    for (int st = 256; st > 0; st >>= 1) {
        if (tid < st) hs[tid] += hs[tid + st];
        __syncthreads();
    }
    if (tid == 0) out[b] = hs[0] + b2[0];
}

// ---------------- launch ----------------
extern "C" void kernel_launch(void* const* d_in, const int* in_sizes, int n_in,
                              void* d_out, int out_size) {
    const float* x      = (const float*)d_in[0];
    const float* conv_w = (const float*)d_in[1];
    const float* conv_b = (const float*)d_in[2];
    const float* pos_e  = (const float*)d_in[3];
    const float* in_w   = (const float*)d_in[4];
    const float* in_b   = (const float*)d_in[5];
    const float* out_w  = (const float*)d_in[6];
    const float* out_b  = (const float*)d_in[7];
    const float* hw1    = (const float*)d_in[8];
    const float* hb1    = (const float*)d_in[9];
    const float* hw2    = (const float*)d_in[10];
    const float* hb2    = (const float*)d_in[11];

    float* out  = (float*)d_out;            // [8]
    float* attn = out + BATCH;              // [6,4,8,576,576]

    cudaFuncSetAttribute(attn_mma, cudaFuncAttributeMaxDynamicSharedMemorySize, ATTN_SMEM);

    float *im2col_p, *pe_p, *qkv_p, *o_p;
    cudaGetSymbolAddress((void**)&im2col_p, g_im2col);
    cudaGetSymbolAddress((void**)&pe_p,     g_pe);
    cudaGetSymbolAddress((void**)&qkv_p,    g_qkv);
    cudaGetSymbolAddress((void**)&o_p,      g_o);

    // 1) im2col
    {
        long total = (long)NIMG*BATCH*SEQ*KPATCH;
        im2col_k<<<(int)((total + 255)/256), 256>>>(x);
    }
    // 2) patch-embed GEMM per image, + conv_b + pos_enc
    {
        dim3 g(DIM/64, (BATCH*SEQ)/64, NIMG);
        sgemm64<<<g, 256>>>(im2col_p, conv_w, pe_p,
                            BATCH*SEQ, DIM, KPATCH,
                            conv_b, pos_e,
                            (long)BATCH*SEQ*KPATCH, (long)DIM*KPATCH,
                            (long)BATCH*SEQ*DIM, DIM);
    }
    // 3) transformer layers
    for (int l = 0; l < NLAYER; l++) {
        {
            dim3 g((3*DIM)/64, TOK/64, 1);
            sgemm64<<<g, 256>>>(pe_p, in_w + (long)l*3*DIM*DIM, qkv_p,
                                TOK, 3*DIM, DIM,
                                in_b + (long)l*3*DIM, nullptr, 0, 0, 0, 0);
        }
        {
            dim3 g(SEQ/16, NB, 1);
            attn_mma<<<g, 256, ATTN_SMEM>>>(qkv_p, o_p, attn, l);
        }
        {
            dim3 g(DIM/64, TOK/64, 1);
            sgemm64<<<g, 256>>>(o_p, out_w + (long)l*DIM*DIM, pe_p,
                                TOK, DIM, DIM,
                                out_b + (long)l*DIM, nullptr, 0, 0, 0, 0);
        }
    }
    // 4) sequence-mean features + MLP head
    {
        dim3 g(NIMG, BATCH);
        feat_k<<<g, DIM>>>();
    }
    head_k<<<BATCH, MLPDIM>>>(hw1, hb1, hw2, hb2, out);
}